// round 15
// baseline (speedup 1.0000x reference)
#include <cuda_runtime.h>
#include <math.h>
#include <stdint.h>

// ---------------------------------------------------------------------------
// InnerConvexViolationProjection — GB300 sm_103a, round 15
// = Round 14 (st.async exchange — best: 285us) with:
//  (1) g exchange packed as st.async.b64: even lane ships cols (t, t+1) in one
//      8-byte async store => 128 remote ops/iter instead of 256.
//  (2) local expect_tx posted immediately after the barrier, before sends.
// ---------------------------------------------------------------------------

#define Mm       256
#define Nn       256
#define HR       128
#define NTH      512
#define KITERS   30
#define PITERS   5

#define MU_IN    1e-3f
#define RHO_C    1e-12f
#define FEAS_TOL 1e-7f
#define EPS_IN   1e-6f

typedef unsigned long long ull;

struct __align__(16) Smem {
    ull   gbar[2];              // ping-pong mbarriers for g exchange (count 1)
    ull   sbar[2];              // ping-pong mbarriers for scalar exchange (count 1)
    ull   gpart2[16][258];      // packed g partials [tile-row][col]
    float x[Nn];                // iterate (SMEM copy for rphase readers)
    float d[Nn];                // power-iter v / stage-2 direction
    __align__(16) float gbuf[2][Nn];   // peer g, double buffered (st.async dst)
    float speer[2];             // peer scalar, double buffered (st.async dst)
    float red[32];
};

// ---- packed f32x2 helpers ----
__device__ __forceinline__ ull pk2(float lo, float hi) {
    ull r; asm("mov.b64 %0, {%1, %2};" : "=l"(r) : "f"(lo), "f"(hi)); return r;
}
__device__ __forceinline__ void unpk2(ull v, float& lo, float& hi) {
    asm("mov.b64 {%0, %1}, %2;" : "=f"(lo), "=f"(hi) : "l"(v));
}
__device__ __forceinline__ void fma2(ull& d, ull a, ull b) {
    asm("fma.rn.f32x2 %0, %1, %2, %3;" : "=l"(d) : "l"(a), "l"(b), "l"(d));
}
__device__ __forceinline__ void add2(ull& d, ull a) {
    asm("add.rn.f32x2 %0, %1, %2;" : "=l"(d) : "l"(d), "l"(a));
}

// ---- cluster / mbarrier helpers ----
__device__ __forceinline__ uint32_t smem_u32(const void* p) {
    return (uint32_t)__cvta_generic_to_shared(const_cast<void*>(p));
}
__device__ __forceinline__ uint32_t mapa_rank(uint32_t a, uint32_t rank) {
    uint32_t r;
    asm("mapa.shared::cluster.u32 %0, %1, %2;" : "=r"(r) : "r"(a), "r"(rank));
    return r;
}
__device__ __forceinline__ void mbar_init(uint32_t a, uint32_t cnt) {
    asm volatile("mbarrier.init.shared.b64 [%0], %1;" :: "r"(a), "r"(cnt) : "memory");
}
// one-shot async stores to peer SMEM with complete_tx on the PEER's mbarrier
__device__ __forceinline__ void st_async_f32(uint32_t dst_cluster, float v,
                                             uint32_t peer_mbar) {
    asm volatile(
        "st.async.shared::cluster.mbarrier::complete_tx::bytes.f32 [%0], %1, [%2];"
        :: "r"(dst_cluster), "f"(v), "r"(peer_mbar) : "memory");
}
__device__ __forceinline__ void st_async_b64(uint32_t dst_cluster, ull v,
                                             uint32_t peer_mbar) {
    asm volatile(
        "st.async.shared::cluster.mbarrier::complete_tx::bytes.b64 [%0], %1, [%2];"
        :: "r"(dst_cluster), "l"(v), "r"(peer_mbar) : "memory");
}
// local expect_tx (+arrive) on our own barrier
__device__ __forceinline__ void mbar_expect_local(uint32_t a, uint32_t bytes) {
    asm volatile("mbarrier.arrive.expect_tx.shared::cta.b64 _, [%0], %1;"
                 :: "r"(a), "r"(bytes) : "memory");
}
__device__ __forceinline__ void mbar_wait(uint32_t a, uint32_t parity) {
    asm volatile(
        "{\n\t.reg .pred P;\n\t"
        "WL_%=:\n\t"
        "mbarrier.try_wait.parity.acquire.cluster.shared::cta.b64 P, [%0], %1, 0x989680;\n\t"
        "@P bra.uni WD_%=;\n\t"
        "bra.uni WL_%=;\n\t"
        "WD_%=:\n\t}"
        :: "r"(a), "r"(parity) : "memory");
}
__device__ __forceinline__ void cluster_sync() {
    asm volatile("barrier.cluster.arrive.aligned;" ::: "memory");
    asm volatile("barrier.cluster.wait.aligned;"   ::: "memory");
}

// ---- block reductions over 512 threads ----
__device__ __forceinline__ float reduce_sum(float* red, int t, float v) {
    #pragma unroll
    for (int o = 16; o > 0; o >>= 1) v += __shfl_xor_sync(0xffffffffu, v, o);
    if ((t & 31) == 0) red[t >> 5] = v;
    __syncthreads();
    if (t < 32) {
        float s = (t < 16) ? red[t] : 0.f;
        #pragma unroll
        for (int o = 8; o > 0; o >>= 1) s += __shfl_xor_sync(0xffffffffu, s, o);
        if (t == 0) red[16] = s;
    }
    __syncthreads();
    return red[16];
}
__device__ __forceinline__ float reduce_max(float* red, int t, float v) {
    #pragma unroll
    for (int o = 16; o > 0; o >>= 1) v = fmaxf(v, __shfl_xor_sync(0xffffffffu, v, o));
    if ((t & 31) == 0) red[t >> 5] = v;
    __syncthreads();
    if (t < 32) {
        float s = (t < 16) ? red[t] : -INFINITY;
        #pragma unroll
        for (int o = 8; o > 0; o >>= 1) s = fmaxf(s, __shfl_xor_sync(0xffffffffu, s, o));
        if (t == 0) red[16] = s;
    }
    __syncthreads();
    return red[16];
}
__device__ __forceinline__ float reduce_min(float* red, int t, float v) {
    #pragma unroll
    for (int o = 16; o > 0; o >>= 1) v = fminf(v, __shfl_xor_sync(0xffffffffu, v, o));
    if ((t & 31) == 0) red[t >> 5] = v;
    __syncthreads();
    if (t < 32) {
        float s = (t < 16) ? red[t] : INFINITY;
        #pragma unroll
        for (int o = 8; o > 0; o >>= 1) s = fminf(s, __shfl_xor_sync(0xffffffffu, s, o));
        if (t == 0) red[16] = s;
    }
    __syncthreads();
    return red[16];
}

// rows direction fma: r2[ip] = packed partial for rows (2ip, 2ip+1) over this
// lane's 8 columns {lane + 32k}.
__device__ __forceinline__ void rphase_fma(const ull Apk[8][4],
                                           const float* __restrict__ vec,
                                           int lane, ull r2[4]) {
    r2[0] = r2[1] = r2[2] = r2[3] = 0ull;
    #pragma unroll
    for (int k = 0; k < 8; k++) {
        float xv = vec[lane + 32 * k];
        ull xx = pk2(xv, xv);
        #pragma unroll
        for (int ip = 0; ip < 4; ip++) fma2(r2[ip], Apk[k][ip], xx);
    }
}

// reduce-scatter (xor 16/8/4/2/1 pairing tree => same sums as full butterfly).
// Returns the full A·vec dot for row (lane>>2)&7.
__device__ __forceinline__ float rscatter(ull r2[4], int lane) {
    const bool b4 = (lane & 16) != 0;
    ull k0 = b4 ? r2[2] : r2[0];
    ull k1 = b4 ? r2[3] : r2[1];
    ull s0 = b4 ? r2[0] : r2[2];
    ull s1 = b4 ? r2[1] : r2[3];
    s0 = __shfl_xor_sync(0xffffffffu, s0, 16);
    s1 = __shfl_xor_sync(0xffffffffu, s1, 16);
    add2(k0, s0); add2(k1, s1);
    const bool b3 = (lane & 8) != 0;
    ull k = b3 ? k1 : k0;
    ull s = b3 ? k0 : k1;
    s = __shfl_xor_sync(0xffffffffu, s, 8);
    add2(k, s);
    float lo, hi; unpk2(k, lo, hi);
    const bool b2 = (lane & 4) != 0;
    float kf = b2 ? hi : lo;
    float sf = b2 ? lo : hi;
    kf += __shfl_xor_sync(0xffffffffu, sf, 4);
    kf += __shfl_xor_sync(0xffffffffu, kf, 2);
    kf += __shfl_xor_sync(0xffffffffu, kf, 1);
    return kf;
}

// broadcast the warp's 8 row values via index shuffles (lane 4v owns row v)
__device__ __forceinline__ void u_broadcast(float val, ull u2[4]) {
    #pragma unroll
    for (int ip = 0; ip < 4; ip++) {
        float lo = __shfl_sync(0xffffffffu, val, (2 * ip) << 2);
        float hi = __shfl_sync(0xffffffffu, val, (2 * ip + 1) << 2);
        u2[ip] = pk2(lo, hi);
    }
}

// cols direction: packed per-col contribution of the thread's 8 rows
__device__ __forceinline__ void gphase(const ull Apk[8][4], const ull u2[4],
                                       Smem& sm, int lane, int w) {
    #pragma unroll
    for (int k = 0; k < 8; k++) {
        ull acc = 0ull;
        #pragma unroll
        for (int ip = 0; ip < 4; ip++) fma2(acc, Apk[k][ip], u2[ip]);
        sm.gpart2[w][lane + 32 * k] = acc;
    }
}

// own-half g for col j: add2 the 16 packed partials, hadd once
__device__ __forceinline__ float gsum16(Smem& sm, int j) {
    ull a0 = 0ull, a1 = 0ull, a2 = 0ull, a3 = 0ull;
    #pragma unroll
    for (int w2 = 0; w2 < 16; w2 += 4) {
        add2(a0, sm.gpart2[w2 + 0][j]);
        add2(a1, sm.gpart2[w2 + 1][j]);
        add2(a2, sm.gpart2[w2 + 2][j]);
        add2(a3, sm.gpart2[w2 + 3][j]);
    }
    add2(a0, a1); add2(a2, a3); add2(a0, a2);
    float lo, hi; unpk2(a0, lo, hi);
    return lo + hi;
}

__global__ void __cluster_dims__(2, 1, 1) __launch_bounds__(NTH, 1)
proj_kernel(const float* __restrict__ x_g, const float* __restrict__ A_g,
            const float* __restrict__ b_g, float* __restrict__ out_g)
{
    extern __shared__ __align__(16) unsigned char smem_raw[];
    Smem& sm = *reinterpret_cast<Smem*>(smem_raw);

    const int t    = threadIdx.x;
    const int lane = t & 31;
    const int w    = t >> 5;            // tile-row: rows [8w, 8w+8)
    const int rg   = (lane >> 2) & 7;   // owned row within tile after rscatter
    const int rank = blockIdx.x & 1;
    const int prob = blockIdx.x >> 1;

    const uint32_t peer      = rank ^ 1;
    const uint32_t gbar_loc0 = smem_u32(&sm.gbar[0]);
    const uint32_t gbar_loc1 = smem_u32(&sm.gbar[1]);
    const uint32_t sbar_loc0 = smem_u32(&sm.sbar[0]);
    const uint32_t sbar_loc1 = smem_u32(&sm.sbar[1]);
    const uint32_t gbar_rem0 = mapa_rank(gbar_loc0, peer);
    const uint32_t gbar_rem1 = mapa_rank(gbar_loc1, peer);
    const uint32_t sbar_rem0 = mapa_rank(sbar_loc0, peer);
    const uint32_t sbar_rem1 = mapa_rank(sbar_loc1, peer);
    const uint32_t gbuf_rem0 = mapa_rank(smem_u32(&sm.gbuf[0][0]), peer);
    const uint32_t gbuf_rem1 = mapa_rank(smem_u32(&sm.gbuf[1][0]), peer);
    const uint32_t speer_rem = mapa_rank(smem_u32(&sm.speer[0]), peer);

    if (t == 0) {
        mbar_init(gbar_loc0, 1);   // single local expect_tx arrive per phase
        mbar_init(gbar_loc1, 1);
        mbar_init(sbar_loc0, 1);
        mbar_init(sbar_loc1, 1);
    }
    // x and x0 live in registers of threads 0..255
    float xreg = 0.f, x0reg = 0.f;
    if (t < Nn) {
        xreg = x_g[(size_t)prob * Nn + t];
        x0reg = xreg;
        sm.x[t] = xreg;
        sm.d[t] = 0.0625f;
    }
    __syncthreads();
    cluster_sync();   // mbarrier init visible cluster-wide before any st.async

    // ---- load + row-normalize own 8x8 tile; per-lane bw for owned row ----
    ull Apk[8][4];
    float bw_own = 0.f;
    {
        const float* Ap = A_g + (size_t)prob * (Mm * Nn)
                        + ((size_t)(rank * HR + w * 8)) * Nn + lane;
        const float* Bp = b_g + (size_t)prob * Mm + rank * HR + w * 8;
        #pragma unroll
        for (int ip = 0; ip < 4; ip++) {
            float a0[8], a1[8];
            float s0 = 0.f, s1 = 0.f;
            #pragma unroll
            for (int k = 0; k < 8; k++) {
                a0[k] = Ap[(size_t)(2 * ip) * Nn + 32 * k];
                a1[k] = Ap[(size_t)(2 * ip + 1) * Nn + 32 * k];
                s0 = fmaf(a0[k], a0[k], s0);
                s1 = fmaf(a1[k], a1[k], s1);
            }
            #pragma unroll
            for (int o = 16; o > 0; o >>= 1) {
                s0 += __shfl_xor_sync(0xffffffffu, s0, o);
                s1 += __shfl_xor_sync(0xffffffffu, s1, o);
            }
            float rn0 = fmaxf(sqrtf(s0), 1e-12f);
            float rn1 = fmaxf(sqrtf(s1), 1e-12f);
            #pragma unroll
            for (int k = 0; k < 8; k++)
                Apk[k][ip] = pk2(a0[k] / rn0, a1[k] / rn1);
            float bv0 = Bp[2 * ip + 0] / rn0;
            float bv1 = Bp[2 * ip + 1] / rn1;
            if (rg == 2 * ip)     bw_own = bv0;
            if (rg == 2 * ip + 1) bw_own = bv1;
        }
    }
    const float bt_own = bw_own - MU_IN;
    __syncthreads();

    int ground = 0;   // bar = ground&1, parity = (ground>>1)&1
    int sround = 0;
    ull r2[4], u2[4];

    // ================= power iteration =================
    for (int it = 0; it < PITERS; it++) {
        rphase_fma(Apk, sm.d, lane, r2);
        float av = rscatter(r2, lane);
        u_broadcast(av, u2);
        gphase(Apk, u2, sm, lane, w);
        __syncthreads();
        int slot = ground & 1;
        uint32_t gbl = slot ? gbar_loc1 : gbar_loc0;
        if (t == 0) mbar_expect_local(gbl, Nn * 4);
        float gj = 0.f, wj = 0.f;
        if (t < Nn) {
            gj = gsum16(sm, t);
            float gnb = __shfl_xor_sync(0xffffffffu, gj, 1);
            if ((t & 1) == 0)
                st_async_b64((slot ? gbuf_rem1 : gbuf_rem0) + (uint32_t)(t * 4),
                             pk2(gj, gnb), slot ? gbar_rem1 : gbar_rem0);
        }
        if (t < Nn) {
            mbar_wait(gbl, (uint32_t)((ground >> 1) & 1));
            wj = gj + sm.gbuf[slot][t];
        }
        ground++;
        float s = reduce_sum(sm.red, t, wj * wj);
        if (t < Nn) sm.d[t] = wj / (sqrtf(s) + 1e-12f);
        __syncthreads();
    }

    // ================= eta =================
    float eta;
    {
        rphase_fma(Apk, sm.d, lane, r2);
        float av = rscatter(r2, lane);
        float ss = ((lane & 3) == 0) ? av * av : 0.f;
        float sown = reduce_sum(sm.red, t, ss);
        int slot = sround & 1;
        uint32_t sbl = slot ? sbar_loc1 : sbar_loc0;
        if (t == 0) {
            mbar_expect_local(sbl, 4);
            st_async_f32(speer_rem + (uint32_t)(slot * 4), sown,
                         slot ? sbar_rem1 : sbar_rem0);
        }
        mbar_wait(sbl, (uint32_t)((sround >> 1) & 1));
        sround++;
        eta = 1.0f / ((sown + sm.speer[slot]) + RHO_C);
    }

    // ================= K-step UVP =================
    for (int it = 0; it < KITERS; it++) {
        rphase_fma(Apk, sm.x, lane, r2);
        float r = rscatter(r2, lane);
        float uval = fmaxf(r - bt_own, 0.f);
        u_broadcast(uval, u2);
        gphase(Apk, u2, sm, lane, w);
        __syncthreads();
        int slot = ground & 1;
        uint32_t gbl = slot ? gbar_loc1 : gbar_loc0;
        if (t == 0) mbar_expect_local(gbl, Nn * 4);
        float gj = 0.f;
        if (t < Nn) {
            gj = gsum16(sm, t);
            float gnb = __shfl_xor_sync(0xffffffffu, gj, 1);
            if ((t & 1) == 0)
                st_async_b64((slot ? gbuf_rem1 : gbuf_rem0) + (uint32_t)(t * 4),
                             pk2(gj, gnb), slot ? gbar_rem1 : gbar_rem0);
        }
        if (t < Nn) {
            mbar_wait(gbl, (uint32_t)((ground >> 1) & 1));
            xreg = fmaf(-eta, gj + sm.gbuf[slot][t], xreg);
            sm.x[t] = xreg;
        }
        ground++;
        __syncthreads();
    }

    // ================= stage 2: gate + alpha =================
    rphase_fma(Apk, sm.x, lane, r2);
    const float ax_own = rscatter(r2, lane);
    float vm = fmaxf(ax_own - bw_own, 0.f);
    float mvown = reduce_max(sm.red, t, vm);
    float maxviol;
    {
        int slot = sround & 1;
        uint32_t sbl = slot ? sbar_loc1 : sbar_loc0;
        if (t == 0) {
            mbar_expect_local(sbl, 4);
            st_async_f32(speer_rem + (uint32_t)(slot * 4), mvown,
                         slot ? sbar_rem1 : sbar_rem0);
        }
        mbar_wait(sbl, (uint32_t)((sround >> 1) & 1));
        sround++;
        maxviol = fmaxf(mvown, sm.speer[slot]);
    }
    const bool do_alpha = (maxviol <= FEAS_TOL);

    float dreg = x0reg - xreg;
    if (t < Nn) sm.d[t] = dreg;
    __syncthreads();
    rphase_fma(Apk, sm.d, lane, r2);
    const float ad_own = rscatter(r2, lane);
    float aown = (ad_own > 0.f) ? (bw_own - ax_own) / (ad_own + 1e-12f) : INFINITY;
    float amin = reduce_min(sm.red, t, aown);
    float alpha;
    {
        int slot = sround & 1;
        uint32_t sbl = slot ? sbar_loc1 : sbar_loc0;
        if (t == 0) {
            mbar_expect_local(sbl, 4);
            st_async_f32(speer_rem + (uint32_t)(slot * 4), amin,
                         slot ? sbar_rem1 : sbar_rem0);
        }
        mbar_wait(sbl, (uint32_t)((sround >> 1) & 1));
        sround++;
        alpha = fminf(amin, sm.speer[slot]);
    }
    if (!isfinite(alpha)) alpha = 1.0f;
    alpha = fminf(fmaxf(alpha - EPS_IN, 0.f), 1.f);

    if (rank == 0 && t < Nn) {
        float o = do_alpha ? (xreg + alpha * dreg) : xreg;
        out_g[(size_t)prob * Nn + t] = o;
    }

    cluster_sync();   // no CTA exits while peer traffic may be in flight
}

extern "C" void kernel_launch(void* const* d_in, const int* in_sizes, int n_in,
                              void* d_out, int out_size) {
    const float* x = (const float*)d_in[0];
    const float* A = (const float*)d_in[1];
    const float* b = (const float*)d_in[2];
    float* out = (float*)d_out;

    const int nprob = in_sizes[0] / Nn;   // B*S
    cudaFuncSetAttribute(proj_kernel, cudaFuncAttributeMaxDynamicSharedMemorySize,
                         (int)sizeof(Smem));
    proj_kernel<<<nprob * 2, NTH, sizeof(Smem)>>>(x, A, b, out);
}

// round 16
// speedup vs baseline: 1.0955x; 1.0955x over previous
#include <cuda_runtime.h>
#include <math.h>
#include <stdint.h>

// ---------------------------------------------------------------------------
// InnerConvexViolationProjection — GB300 sm_103a, round 16
// = Round 14 (st.async exchange, 285us champion) +
//  (1) gpart stored as f32 (hadd in gphase, STS.32): halves the gpart SMEM
//      round-trip traffic (32KB+32KB -> 16KB+16KB per iteration).
//  (2) local expect_tx posted right after the barrier, before any sends.
// Exchange stays scalar st.async.f32 per column (R15's b64 packing regressed).
// ---------------------------------------------------------------------------

#define Mm       256
#define Nn       256
#define HR       128
#define NTH      512
#define KITERS   30
#define PITERS   5

#define MU_IN    1e-3f
#define RHO_C    1e-12f
#define FEAS_TOL 1e-7f
#define EPS_IN   1e-6f

typedef unsigned long long ull;

struct __align__(16) Smem {
    ull   gbar[2];              // ping-pong mbarriers for g exchange (count 1)
    ull   sbar[2];              // ping-pong mbarriers for scalar exchange (count 1)
    float gpart[16][260];       // f32 g partials [tile-row][col]
    float x[Nn];                // iterate (SMEM copy for rphase readers)
    float d[Nn];                // power-iter v / stage-2 direction
    __align__(16) float gbuf[2][Nn];   // peer g, double buffered (st.async dst)
    float speer[2];             // peer scalar, double buffered (st.async dst)
    float red[32];
};

// ---- packed f32x2 helpers ----
__device__ __forceinline__ ull pk2(float lo, float hi) {
    ull r; asm("mov.b64 %0, {%1, %2};" : "=l"(r) : "f"(lo), "f"(hi)); return r;
}
__device__ __forceinline__ void unpk2(ull v, float& lo, float& hi) {
    asm("mov.b64 {%0, %1}, %2;" : "=f"(lo), "=f"(hi) : "l"(v));
}
__device__ __forceinline__ void fma2(ull& d, ull a, ull b) {
    asm("fma.rn.f32x2 %0, %1, %2, %3;" : "=l"(d) : "l"(a), "l"(b), "l"(d));
}
__device__ __forceinline__ void add2(ull& d, ull a) {
    asm("add.rn.f32x2 %0, %1, %2;" : "=l"(d) : "l"(d), "l"(a));
}

// ---- cluster / mbarrier helpers ----
__device__ __forceinline__ uint32_t smem_u32(const void* p) {
    return (uint32_t)__cvta_generic_to_shared(const_cast<void*>(p));
}
__device__ __forceinline__ uint32_t mapa_rank(uint32_t a, uint32_t rank) {
    uint32_t r;
    asm("mapa.shared::cluster.u32 %0, %1, %2;" : "=r"(r) : "r"(a), "r"(rank));
    return r;
}
__device__ __forceinline__ void mbar_init(uint32_t a, uint32_t cnt) {
    asm volatile("mbarrier.init.shared.b64 [%0], %1;" :: "r"(a), "r"(cnt) : "memory");
}
// one-shot async store to peer SMEM with complete_tx on the PEER's mbarrier
__device__ __forceinline__ void st_async_f32(uint32_t dst_cluster, float v,
                                             uint32_t peer_mbar) {
    asm volatile(
        "st.async.shared::cluster.mbarrier::complete_tx::bytes.f32 [%0], %1, [%2];"
        :: "r"(dst_cluster), "f"(v), "r"(peer_mbar) : "memory");
}
// local expect_tx (+arrive) on our own barrier
__device__ __forceinline__ void mbar_expect_local(uint32_t a, uint32_t bytes) {
    asm volatile("mbarrier.arrive.expect_tx.shared::cta.b64 _, [%0], %1;"
                 :: "r"(a), "r"(bytes) : "memory");
}
__device__ __forceinline__ void mbar_wait(uint32_t a, uint32_t parity) {
    asm volatile(
        "{\n\t.reg .pred P;\n\t"
        "WL_%=:\n\t"
        "mbarrier.try_wait.parity.acquire.cluster.shared::cta.b64 P, [%0], %1, 0x989680;\n\t"
        "@P bra.uni WD_%=;\n\t"
        "bra.uni WL_%=;\n\t"
        "WD_%=:\n\t}"
        :: "r"(a), "r"(parity) : "memory");
}
__device__ __forceinline__ void cluster_sync() {
    asm volatile("barrier.cluster.arrive.aligned;" ::: "memory");
    asm volatile("barrier.cluster.wait.aligned;"   ::: "memory");
}

// ---- block reductions over 512 threads ----
__device__ __forceinline__ float reduce_sum(float* red, int t, float v) {
    #pragma unroll
    for (int o = 16; o > 0; o >>= 1) v += __shfl_xor_sync(0xffffffffu, v, o);
    if ((t & 31) == 0) red[t >> 5] = v;
    __syncthreads();
    if (t < 32) {
        float s = (t < 16) ? red[t] : 0.f;
        #pragma unroll
        for (int o = 8; o > 0; o >>= 1) s += __shfl_xor_sync(0xffffffffu, s, o);
        if (t == 0) red[16] = s;
    }
    __syncthreads();
    return red[16];
}
__device__ __forceinline__ float reduce_max(float* red, int t, float v) {
    #pragma unroll
    for (int o = 16; o > 0; o >>= 1) v = fmaxf(v, __shfl_xor_sync(0xffffffffu, v, o));
    if ((t & 31) == 0) red[t >> 5] = v;
    __syncthreads();
    if (t < 32) {
        float s = (t < 16) ? red[t] : -INFINITY;
        #pragma unroll
        for (int o = 8; o > 0; o >>= 1) s = fmaxf(s, __shfl_xor_sync(0xffffffffu, s, o));
        if (t == 0) red[16] = s;
    }
    __syncthreads();
    return red[16];
}
__device__ __forceinline__ float reduce_min(float* red, int t, float v) {
    #pragma unroll
    for (int o = 16; o > 0; o >>= 1) v = fminf(v, __shfl_xor_sync(0xffffffffu, v, o));
    if ((t & 31) == 0) red[t >> 5] = v;
    __syncthreads();
    if (t < 32) {
        float s = (t < 16) ? red[t] : INFINITY;
        #pragma unroll
        for (int o = 8; o > 0; o >>= 1) s = fminf(s, __shfl_xor_sync(0xffffffffu, s, o));
        if (t == 0) red[16] = s;
    }
    __syncthreads();
    return red[16];
}

// rows direction fma: r2[ip] = packed partial for rows (2ip, 2ip+1) over this
// lane's 8 columns {lane + 32k}.
__device__ __forceinline__ void rphase_fma(const ull Apk[8][4],
                                           const float* __restrict__ vec,
                                           int lane, ull r2[4]) {
    r2[0] = r2[1] = r2[2] = r2[3] = 0ull;
    #pragma unroll
    for (int k = 0; k < 8; k++) {
        float xv = vec[lane + 32 * k];
        ull xx = pk2(xv, xv);
        #pragma unroll
        for (int ip = 0; ip < 4; ip++) fma2(r2[ip], Apk[k][ip], xx);
    }
}

// reduce-scatter (xor 16/8/4/2/1 pairing tree => same sums as full butterfly).
// Returns the full A·vec dot for row (lane>>2)&7.
__device__ __forceinline__ float rscatter(ull r2[4], int lane) {
    const bool b4 = (lane & 16) != 0;
    ull k0 = b4 ? r2[2] : r2[0];
    ull k1 = b4 ? r2[3] : r2[1];
    ull s0 = b4 ? r2[0] : r2[2];
    ull s1 = b4 ? r2[1] : r2[3];
    s0 = __shfl_xor_sync(0xffffffffu, s0, 16);
    s1 = __shfl_xor_sync(0xffffffffu, s1, 16);
    add2(k0, s0); add2(k1, s1);
    const bool b3 = (lane & 8) != 0;
    ull k = b3 ? k1 : k0;
    ull s = b3 ? k0 : k1;
    s = __shfl_xor_sync(0xffffffffu, s, 8);
    add2(k, s);
    float lo, hi; unpk2(k, lo, hi);
    const bool b2 = (lane & 4) != 0;
    float kf = b2 ? hi : lo;
    float sf = b2 ? lo : hi;
    kf += __shfl_xor_sync(0xffffffffu, sf, 4);
    kf += __shfl_xor_sync(0xffffffffu, kf, 2);
    kf += __shfl_xor_sync(0xffffffffu, kf, 1);
    return kf;
}

// broadcast the warp's 8 row values via index shuffles (lane 4v owns row v)
__device__ __forceinline__ void u_broadcast(float val, ull u2[4]) {
    #pragma unroll
    for (int ip = 0; ip < 4; ip++) {
        float lo = __shfl_sync(0xffffffffu, val, (2 * ip) << 2);
        float hi = __shfl_sync(0xffffffffu, val, (2 * ip + 1) << 2);
        u2[ip] = pk2(lo, hi);
    }
}

// cols direction: per-col contribution of the thread's 8 rows, hadd in reg,
// stored as f32 (halves gpart SMEM traffic vs packed).
__device__ __forceinline__ void gphase(const ull Apk[8][4], const ull u2[4],
                                       Smem& sm, int lane, int w) {
    #pragma unroll
    for (int k = 0; k < 8; k++) {
        ull acc = 0ull;
        #pragma unroll
        for (int ip = 0; ip < 4; ip++) fma2(acc, Apk[k][ip], u2[ip]);
        float lo, hi; unpk2(acc, lo, hi);
        sm.gpart[w][lane + 32 * k] = lo + hi;
    }
}

// own-half g for col j: sum the 16 f32 warp partials
__device__ __forceinline__ float gsum16(Smem& sm, int j) {
    float a0 = 0.f, a1 = 0.f, a2 = 0.f, a3 = 0.f;
    #pragma unroll
    for (int w2 = 0; w2 < 16; w2 += 4) {
        a0 += sm.gpart[w2 + 0][j];
        a1 += sm.gpart[w2 + 1][j];
        a2 += sm.gpart[w2 + 2][j];
        a3 += sm.gpart[w2 + 3][j];
    }
    return (a0 + a1) + (a2 + a3);
}

__global__ void __cluster_dims__(2, 1, 1) __launch_bounds__(NTH, 1)
proj_kernel(const float* __restrict__ x_g, const float* __restrict__ A_g,
            const float* __restrict__ b_g, float* __restrict__ out_g)
{
    extern __shared__ __align__(16) unsigned char smem_raw[];
    Smem& sm = *reinterpret_cast<Smem*>(smem_raw);

    const int t    = threadIdx.x;
    const int lane = t & 31;
    const int w    = t >> 5;            // tile-row: rows [8w, 8w+8)
    const int rg   = (lane >> 2) & 7;   // owned row within tile after rscatter
    const int rank = blockIdx.x & 1;
    const int prob = blockIdx.x >> 1;

    const uint32_t peer      = rank ^ 1;
    const uint32_t gbar_loc0 = smem_u32(&sm.gbar[0]);
    const uint32_t gbar_loc1 = smem_u32(&sm.gbar[1]);
    const uint32_t sbar_loc0 = smem_u32(&sm.sbar[0]);
    const uint32_t sbar_loc1 = smem_u32(&sm.sbar[1]);
    const uint32_t gbar_rem0 = mapa_rank(gbar_loc0, peer);
    const uint32_t gbar_rem1 = mapa_rank(gbar_loc1, peer);
    const uint32_t sbar_rem0 = mapa_rank(sbar_loc0, peer);
    const uint32_t sbar_rem1 = mapa_rank(sbar_loc1, peer);
    const uint32_t gbuf_rem0 = mapa_rank(smem_u32(&sm.gbuf[0][0]), peer);
    const uint32_t gbuf_rem1 = mapa_rank(smem_u32(&sm.gbuf[1][0]), peer);
    const uint32_t speer_rem = mapa_rank(smem_u32(&sm.speer[0]), peer);

    if (t == 0) {
        mbar_init(gbar_loc0, 1);   // single local expect_tx arrive per phase
        mbar_init(gbar_loc1, 1);
        mbar_init(sbar_loc0, 1);
        mbar_init(sbar_loc1, 1);
    }
    // x and x0 live in registers of threads 0..255
    float xreg = 0.f, x0reg = 0.f;
    if (t < Nn) {
        xreg = x_g[(size_t)prob * Nn + t];
        x0reg = xreg;
        sm.x[t] = xreg;
        sm.d[t] = 0.0625f;
    }
    __syncthreads();
    cluster_sync();   // mbarrier init visible cluster-wide before any st.async

    // ---- load + row-normalize own 8x8 tile; per-lane bw for owned row ----
    ull Apk[8][4];
    float bw_own = 0.f;
    {
        const float* Ap = A_g + (size_t)prob * (Mm * Nn)
                        + ((size_t)(rank * HR + w * 8)) * Nn + lane;
        const float* Bp = b_g + (size_t)prob * Mm + rank * HR + w * 8;
        #pragma unroll
        for (int ip = 0; ip < 4; ip++) {
            float a0[8], a1[8];
            float s0 = 0.f, s1 = 0.f;
            #pragma unroll
            for (int k = 0; k < 8; k++) {
                a0[k] = Ap[(size_t)(2 * ip) * Nn + 32 * k];
                a1[k] = Ap[(size_t)(2 * ip + 1) * Nn + 32 * k];
                s0 = fmaf(a0[k], a0[k], s0);
                s1 = fmaf(a1[k], a1[k], s1);
            }
            #pragma unroll
            for (int o = 16; o > 0; o >>= 1) {
                s0 += __shfl_xor_sync(0xffffffffu, s0, o);
                s1 += __shfl_xor_sync(0xffffffffu, s1, o);
            }
            float rn0 = fmaxf(sqrtf(s0), 1e-12f);
            float rn1 = fmaxf(sqrtf(s1), 1e-12f);
            #pragma unroll
            for (int k = 0; k < 8; k++)
                Apk[k][ip] = pk2(a0[k] / rn0, a1[k] / rn1);
            float bv0 = Bp[2 * ip + 0] / rn0;
            float bv1 = Bp[2 * ip + 1] / rn1;
            if (rg == 2 * ip)     bw_own = bv0;
            if (rg == 2 * ip + 1) bw_own = bv1;
        }
    }
    const float bt_own = bw_own - MU_IN;
    __syncthreads();

    int ground = 0;   // bar = ground&1, parity = (ground>>1)&1
    int sround = 0;
    ull r2[4], u2[4];

    // ================= power iteration =================
    for (int it = 0; it < PITERS; it++) {
        rphase_fma(Apk, sm.d, lane, r2);
        float av = rscatter(r2, lane);
        u_broadcast(av, u2);
        gphase(Apk, u2, sm, lane, w);
        __syncthreads();
        int slot = ground & 1;
        uint32_t gbl = slot ? gbar_loc1 : gbar_loc0;
        if (t == 0) mbar_expect_local(gbl, Nn * 4);
        float gj = 0.f, wj = 0.f;
        if (t < Nn) {
            gj = gsum16(sm, t);
            st_async_f32((slot ? gbuf_rem1 : gbuf_rem0) + (uint32_t)(t * 4), gj,
                         slot ? gbar_rem1 : gbar_rem0);
        }
        if (t < Nn) {
            mbar_wait(gbl, (uint32_t)((ground >> 1) & 1));
            wj = gj + sm.gbuf[slot][t];
        }
        ground++;
        float s = reduce_sum(sm.red, t, wj * wj);
        if (t < Nn) sm.d[t] = wj / (sqrtf(s) + 1e-12f);
        __syncthreads();
    }

    // ================= eta =================
    float eta;
    {
        rphase_fma(Apk, sm.d, lane, r2);
        float av = rscatter(r2, lane);
        float ss = ((lane & 3) == 0) ? av * av : 0.f;
        float sown = reduce_sum(sm.red, t, ss);
        int slot = sround & 1;
        uint32_t sbl = slot ? sbar_loc1 : sbar_loc0;
        if (t == 0) {
            mbar_expect_local(sbl, 4);
            st_async_f32(speer_rem + (uint32_t)(slot * 4), sown,
                         slot ? sbar_rem1 : sbar_rem0);
        }
        mbar_wait(sbl, (uint32_t)((sround >> 1) & 1));
        sround++;
        eta = 1.0f / ((sown + sm.speer[slot]) + RHO_C);
    }

    // ================= K-step UVP =================
    for (int it = 0; it < KITERS; it++) {
        rphase_fma(Apk, sm.x, lane, r2);
        float r = rscatter(r2, lane);
        float uval = fmaxf(r - bt_own, 0.f);
        u_broadcast(uval, u2);
        gphase(Apk, u2, sm, lane, w);
        __syncthreads();
        int slot = ground & 1;
        uint32_t gbl = slot ? gbar_loc1 : gbar_loc0;
        if (t == 0) mbar_expect_local(gbl, Nn * 4);
        float gj = 0.f;
        if (t < Nn) {
            gj = gsum16(sm, t);
            st_async_f32((slot ? gbuf_rem1 : gbuf_rem0) + (uint32_t)(t * 4), gj,
                         slot ? gbar_rem1 : gbar_rem0);
        }
        if (t < Nn) {
            mbar_wait(gbl, (uint32_t)((ground >> 1) & 1));
            xreg = fmaf(-eta, gj + sm.gbuf[slot][t], xreg);
            sm.x[t] = xreg;
        }
        ground++;
        __syncthreads();
    }

    // ================= stage 2: gate + alpha =================
    rphase_fma(Apk, sm.x, lane, r2);
    const float ax_own = rscatter(r2, lane);
    float vm = fmaxf(ax_own - bw_own, 0.f);
    float mvown = reduce_max(sm.red, t, vm);
    float maxviol;
    {
        int slot = sround & 1;
        uint32_t sbl = slot ? sbar_loc1 : sbar_loc0;
        if (t == 0) {
            mbar_expect_local(sbl, 4);
            st_async_f32(speer_rem + (uint32_t)(slot * 4), mvown,
                         slot ? sbar_rem1 : sbar_rem0);
        }
        mbar_wait(sbl, (uint32_t)((sround >> 1) & 1));
        sround++;
        maxviol = fmaxf(mvown, sm.speer[slot]);
    }
    const bool do_alpha = (maxviol <= FEAS_TOL);

    float dreg = x0reg - xreg;
    if (t < Nn) sm.d[t] = dreg;
    __syncthreads();
    rphase_fma(Apk, sm.d, lane, r2);
    const float ad_own = rscatter(r2, lane);
    float aown = (ad_own > 0.f) ? (bw_own - ax_own) / (ad_own + 1e-12f) : INFINITY;
    float amin = reduce_min(sm.red, t, aown);
    float alpha;
    {
        int slot = sround & 1;
        uint32_t sbl = slot ? sbar_loc1 : sbar_loc0;
        if (t == 0) {
            mbar_expect_local(sbl, 4);
            st_async_f32(speer_rem + (uint32_t)(slot * 4), amin,
                         slot ? sbar_rem1 : sbar_rem0);
        }
        mbar_wait(sbl, (uint32_t)((sround >> 1) & 1));
        sround++;
        alpha = fminf(amin, sm.speer[slot]);
    }
    if (!isfinite(alpha)) alpha = 1.0f;
    alpha = fminf(fmaxf(alpha - EPS_IN, 0.f), 1.f);

    if (rank == 0 && t < Nn) {
        float o = do_alpha ? (xreg + alpha * dreg) : xreg;
        out_g[(size_t)prob * Nn + t] = o;
    }

    cluster_sync();   // no CTA exits while peer traffic may be in flight
}

extern "C" void kernel_launch(void* const* d_in, const int* in_sizes, int n_in,
                              void* d_out, int out_size) {
    const float* x = (const float*)d_in[0];
    const float* A = (const float*)d_in[1];
    const float* b = (const float*)d_in[2];
    float* out = (float*)d_out;

    const int nprob = in_sizes[0] / Nn;   // B*S
    cudaFuncSetAttribute(proj_kernel, cudaFuncAttributeMaxDynamicSharedMemorySize,
                         (int)sizeof(Smem));
    proj_kernel<<<nprob * 2, NTH, sizeof(Smem)>>>(x, A, b, out);
}